// round 15
// baseline (speedup 1.0000x reference)
#include <cuda_runtime.h>
#include <cuda_bf16.h>
#include <math.h>
#include <stdint.h>

#define D_MODEL   1024
#define D_STATE   16
#define D_CONV    4
#define D_INNER   2048
#define DT_RANK   64
#define IN_SIZE   512
#define OUT_SIZE  512
#define BATCH     2048
#define XDB_COLS  96
#define STATE_W   20

typedef __nv_bfloat16 bf16;

// ---------------- fp32 scratch ----------------
__device__ float g_xz[BATCH * 2 * D_INNER];
__device__ float g_xdb[BATCH * XDB_COLS];
__device__ float g_bz[2 * D_INNER];
// ---------------- bf16 split scratch ----------------
__device__ bf16 g_x_hi[BATCH * IN_SIZE],   g_x_lo[BATCH * IN_SIZE];
__device__ bf16 g_xc_hi[BATCH * D_INNER],  g_xc_lo[BATCH * D_INNER];
__device__ bf16 g_y_hi[BATCH * D_INNER],   g_y_lo[BATCH * D_INNER];
__device__ bf16 g_wi_hi[IN_SIZE * D_MODEL],     g_wi_lo[IN_SIZE * D_MODEL];
__device__ bf16 g_ip_hi[2 * D_INNER * D_MODEL], g_ip_lo[2 * D_INNER * D_MODEL];
__device__ bf16 g_wxz_hi[2 * D_INNER * IN_SIZE], g_wxz_lo[2 * D_INNER * IN_SIZE];
__device__ bf16 g_w4_hi[XDB_COLS * D_INNER],    g_w4_lo[XDB_COLS * D_INNER];
__device__ bf16 g_opT_hi[D_INNER * D_MODEL],    g_opT_lo[D_INNER * D_MODEL];
__device__ bf16 g_woT_hi[OUT_SIZE * D_MODEL],   g_woT_lo[OUT_SIZE * D_MODEL];
__device__ bf16 g_wf_hi[OUT_SIZE * D_INNER],    g_wf_lo[OUT_SIZE * D_INNER];

// ---------------- helpers ----------------
__device__ __forceinline__ float softplusf(float x) {
    return (x > 0.f) ? (x + log1pf(__expf(-x))) : log1pf(__expf(x));
}
__device__ __forceinline__ float siluf(float x) {
    return x / (1.f + __expf(-x));
}
__device__ __forceinline__ void bsplit(float v, bf16& h, bf16& l) {
    h = __float2bfloat16_rn(v);
    l = __float2bfloat16_rn(v - __bfloat162float(h));
}
__device__ __forceinline__ void mmabf(float* c, const uint32_t* a, const uint32_t* b) {
    asm volatile(
        "mma.sync.aligned.m16n8k16.row.col.f32.bf16.bf16.f32 "
        "{%0,%1,%2,%3}, {%4,%5,%6,%7}, {%8,%9}, {%0,%1,%2,%3};"
        : "+f"(c[0]), "+f"(c[1]), "+f"(c[2]), "+f"(c[3])
        : "r"(a[0]), "r"(a[1]), "r"(a[2]), "r"(a[3]), "r"(b[0]), "r"(b[1]));
}
__device__ __forceinline__ void cpa16(uint32_t dst, const void* src, bool p) {
    int sz = p ? 16 : 0;
    asm volatile("cp.async.cg.shared.global [%0], [%1], 16, %2;\n"
                 :: "r"(dst), "l"(src), "r"(sz));
}
__device__ __forceinline__ void ldm4(uint32_t* r, uint32_t addr) {
    asm volatile("ldmatrix.sync.aligned.m8n8.x4.shared.b16 {%0,%1,%2,%3}, [%4];"
                 : "=r"(r[0]), "=r"(r[1]), "=r"(r[2]), "=r"(r[3]) : "r"(addr));
}

// ======================================================================
// 2xBF16-split tensor GEMM body. C[M,N] = A[M,K] @ B[N,K]^T.
// BM=128, BN=64, BK=64, 256 thr, warps 4(m)x2(n), warp tile 32x32.
// cp.async 2-stage; smem 108KB/CTA -> 2 CTAs/SM. ldmatrix frag loads.
// ======================================================================
#define A_TSZ   (128 * 36)
#define B_TSZ   (64 * 36)
#define TG_STAGE (2 * A_TSZ + 2 * B_TSZ)
#define TG_SMEM  (2 * TG_STAGE * 4)      // 110592 B

template<int EPI, bool SPLITK, bool WSPLIT>
__device__ __forceinline__ void
bgemm_body(uint32_t* smbuf, int bx, int by, int bzz, int gz,
           const bf16* __restrict__ Ahi, const bf16* __restrict__ Alo,
           const bf16* __restrict__ Bhi, const bf16* __restrict__ Blo,
           float* __restrict__ C, bf16* __restrict__ Chi, bf16* __restrict__ Clo,
           const float* __restrict__ bias,
           int M, int N, int K, int lda, int ldb, int ldc)
{
    const uint32_t* A32h = reinterpret_cast<const uint32_t*>(Ahi);
    const uint32_t* A32l = reinterpret_cast<const uint32_t*>(Alo);
    const uint32_t* B32h = reinterpret_cast<const uint32_t*>(Bhi);
    const uint32_t* B32l = reinterpret_cast<const uint32_t*>(Blo);
    const int ldap = lda >> 1, ldbp = ldb >> 1;

    const int tid  = threadIdx.x;
    const int lane = tid & 31;
    const int warp = tid >> 5;
    const int wm   = warp & 3;
    const int wn   = warp >> 2;
    const int m0   = by * 128;
    const int n0   = bx * 64;
    const int Kc   = SPLITK ? (K / gz) : K;
    const int k0b  = SPLITK ? (bzz * Kc) : 0;
    const int T    = Kc / 64;

    const int lr = tid >> 3;
    const int lc = (tid & 7) * 4;

    // ldmatrix lane geometry
    const uint32_t sbase = (uint32_t)__cvta_generic_to_shared(smbuf);
    const int qrow = lane & 15;                     // tile row
    const int kSel = (lane & 16) ? 16 : 0;          // byte offset k8..15

    float acc[2][4][4];
#pragma unroll
    for (int i = 0; i < 2; i++)
#pragma unroll
        for (int j = 0; j < 4; j++)
#pragma unroll
            for (int q = 0; q < 4; q++) acc[i][j][q] = 0.f;

    auto fill = [&](int t, int st) {
        uint32_t* Ah = smbuf + st * TG_STAGE;
        uint32_t* Al = Ah + A_TSZ;
        uint32_t* Bh = Al + A_TSZ;
        uint32_t* Bl = Bh + B_TSZ;
        const int kp0 = (k0b + t * 64) >> 1;
#pragma unroll
        for (int it = 0; it < 4; it++) {
            const int row = lr + it * 32;
            const size_t g = (size_t)(m0 + row) * ldap + kp0 + lc;
            cpa16((uint32_t)__cvta_generic_to_shared(&Ah[row * 36 + lc]), A32h + g, true);
            cpa16((uint32_t)__cvta_generic_to_shared(&Al[row * 36 + lc]), A32l + g, true);
        }
#pragma unroll
        for (int it = 0; it < 2; it++) {
            const int row = lr + it * 32;
            const bool p = SPLITK ? ((n0 + row) < N) : true;
            const size_t g = (size_t)(n0 + row) * ldbp + kp0 + lc;
            cpa16((uint32_t)__cvta_generic_to_shared(&Bh[row * 36 + lc]), B32h + g, p);
            cpa16((uint32_t)__cvta_generic_to_shared(&Bl[row * 36 + lc]), B32l + g, p);
        }
    };

    auto compute = [&](int st) {
        const uint32_t stb = sbase + st * TG_STAGE * 4;
        const uint32_t AhB = stb;
        const uint32_t AlB = stb + A_TSZ * 4;
        const uint32_t BhB = stb + 2 * A_TSZ * 4;
        const uint32_t BlB = BhB + B_TSZ * 4;
#pragma unroll
        for (int sl = 0; sl < 4; sl++) {            // 4 slices of k16
            const int colb = sl * 32 + kSel;        // byte col within row
            uint32_t ah[2][4], al[2][4];
#pragma unroll
            for (int mt = 0; mt < 2; mt++) {
                const uint32_t off = (uint32_t)(wm * 32 + mt * 16 + qrow) * 144 + colb;
                ldm4(ah[mt], AhB + off);
                ldm4(al[mt], AlB + off);
            }
            uint32_t bh[4][2], bl[4][2];
#pragma unroll
            for (int p = 0; p < 2; p++) {           // 2 n-pairs of 16
                const uint32_t off = (uint32_t)(wn * 32 + p * 16 + qrow) * 144 + colb;
                uint32_t t4[4];
                ldm4(t4, BhB + off);
                bh[2*p][0] = t4[0]; bh[2*p+1][0] = t4[1];
                bh[2*p][1] = t4[2]; bh[2*p+1][1] = t4[3];
                ldm4(t4, BlB + off);
                bl[2*p][0] = t4[0]; bl[2*p+1][0] = t4[1];
                bl[2*p][1] = t4[2]; bl[2*p+1][1] = t4[3];
            }
#pragma unroll
            for (int mt = 0; mt < 2; mt++)
#pragma unroll
                for (int nt = 0; nt < 4; nt++) {
                    mmabf(acc[mt][nt], ah[mt], bl[nt]);
                    mmabf(acc[mt][nt], al[mt], bh[nt]);
                    mmabf(acc[mt][nt], ah[mt], bh[nt]);
                }
        }
    };

    fill(0, 0);
    asm volatile("cp.async.commit_group;" ::: "memory");
    for (int t = 0; t < T; t++) {
        if (t + 1 < T) {
            fill(t + 1, (t + 1) & 1);
            asm volatile("cp.async.commit_group;" ::: "memory");
            asm volatile("cp.async.wait_group 1;" ::: "memory");
        } else {
            asm volatile("cp.async.wait_group 0;" ::: "memory");
        }
        __syncthreads();
        compute(t & 1);
        __syncthreads();
    }

#pragma unroll
    for (int mt = 0; mt < 2; mt++) {
        const int mr = m0 + wm * 32 + mt * 16 + (lane >> 2);
#pragma unroll
        for (int nt = 0; nt < 4; nt++) {
            const int nc = n0 + wn * 32 + nt * 8 + (lane & 3) * 2;
            float v0 = acc[mt][nt][0], v1 = acc[mt][nt][1];
            float v2 = acc[mt][nt][2], v3 = acc[mt][nt][3];
            if (SPLITK) {
                if (nc < N) {
                    atomicAdd(&C[(size_t)mr * ldc + nc], v0);
                    atomicAdd(&C[(size_t)mr * ldc + nc + 1], v1);
                    atomicAdd(&C[(size_t)(mr + 8) * ldc + nc], v2);
                    atomicAdd(&C[(size_t)(mr + 8) * ldc + nc + 1], v3);
                }
                continue;
            }
            if (EPI >= 1) {
                const float b0 = bias[nc], b1 = bias[nc + 1];
                v0 += b0; v1 += b1; v2 += b0; v3 += b1;
            }
            if (WSPLIT) {
                bf16 h0, l0, h1, l1, h2, l2, h3, l3;
                bsplit(v0, h0, l0); bsplit(v1, h1, l1);
                bsplit(v2, h2, l2); bsplit(v3, h3, l3);
                __nv_bfloat162 ha = {h0, h1}, hb = {h2, h3};
                __nv_bfloat162 la = {l0, l1}, lb = {l2, l3};
                *reinterpret_cast<uint32_t*>(&Chi[(size_t)mr * ldc + nc])       = *(uint32_t*)&ha;
                *reinterpret_cast<uint32_t*>(&Chi[(size_t)(mr + 8) * ldc + nc]) = *(uint32_t*)&hb;
                *reinterpret_cast<uint32_t*>(&Clo[(size_t)mr * ldc + nc])       = *(uint32_t*)&la;
                *reinterpret_cast<uint32_t*>(&Clo[(size_t)(mr + 8) * ldc + nc]) = *(uint32_t*)&lb;
            } else {
                *reinterpret_cast<float2*>(&C[(size_t)mr * ldc + nc])       = make_float2(v0, v1);
                *reinterpret_cast<float2*>(&C[(size_t)(mr + 8) * ldc + nc]) = make_float2(v2, v3);
            }
        }
    }
}

template<int EPI, bool SPLITK, bool WSPLIT>
__global__ void __launch_bounds__(256, 2)
bgemm(const bf16* __restrict__ Ahi, const bf16* __restrict__ Alo,
      const bf16* __restrict__ Bhi, const bf16* __restrict__ Blo,
      float* __restrict__ C, bf16* __restrict__ Chi, bf16* __restrict__ Clo,
      const float* __restrict__ bias,
      int M, int N, int K, int lda, int ldb, int ldc)
{
    extern __shared__ uint32_t smbuf[];
    bgemm_body<EPI, SPLITK, WSPLIT>(smbuf, blockIdx.x, blockIdx.y, blockIdx.z, gridDim.z,
                                    Ahi, Alo, Bhi, Blo, C, Chi, Clo, bias,
                                    M, N, K, lda, ldb, ldc);
}

// ---- dual weight GEMM: W12 (256 CTAs) + Wf (128 CTAs) in one launch ----
__global__ void __launch_bounds__(256, 2)
wgemm_dual(const bf16* ipH, const bf16* ipL, const bf16* wiH, const bf16* wiL,
           bf16* wxH, bf16* wxL,
           const bf16* woH, const bf16* woL, const bf16* opH, const bf16* opL,
           bf16* wfH, bf16* wfL)
{
    extern __shared__ uint32_t smbuf[];
    const int bid = blockIdx.x;
    if (bid < 256) {
        bgemm_body<0, false, true>(smbuf, bid & 7, bid >> 3, 0, 1,
            ipH, ipL, wiH, wiL, nullptr, wxH, wxL, nullptr,
            2 * D_INNER, IN_SIZE, D_MODEL, D_MODEL, D_MODEL, IN_SIZE);
    } else {
        const int t = bid - 256;
        bgemm_body<0, false, true>(smbuf, t & 31, t >> 5, 0, 1,
            woH, woL, opH, opL, nullptr, wfH, wfL, nullptr,
            OUT_SIZE, D_INNER, D_MODEL, D_MODEL, D_MODEL, D_INNER);
    }
}

// ---------------- split helper ----------------
__device__ __forceinline__ void split4(const float* in, bf16* hi, bf16* lo, int i) {
    float4 v = reinterpret_cast<const float4*>(in)[i];
    bf16 h0, l0, h1, l1, h2, l2, h3, l3;
    bsplit(v.x, h0, l0); bsplit(v.y, h1, l1);
    bsplit(v.z, h2, l2); bsplit(v.w, h3, l3);
    __nv_bfloat162 hA = {h0, h1}, hB = {h2, h3};
    __nv_bfloat162 lA = {l0, l1}, lB = {l2, l3};
    uint2 hu = {*(uint32_t*)&hA, *(uint32_t*)&hB};
    uint2 lu = {*(uint32_t*)&lA, *(uint32_t*)&lB};
    reinterpret_cast<uint2*>(hi)[i] = hu;
    reinterpret_cast<uint2*>(lo)[i] = lu;
}

__device__ __forceinline__ void tsplit_seg(const float* in, bf16* hi, bf16* lo,
                                           int K, int N, int k0, int n0,
                                           int tid, float (*tsm)[33])
{
    const int tx = tid & 31, ty = tid >> 5;
#pragma unroll
    for (int j = ty; j < 32; j += 8)
        tsm[j][tx] = in[(size_t)(k0 + j) * N + n0 + tx];
    __syncthreads();
#pragma unroll
    for (int j = ty; j < 32; j += 8) {
        float v = tsm[tx][j];
        bf16 h, l; bsplit(v, h, l);
        hi[(size_t)(n0 + j) * K + k0 + tx] = h;
        lo[(size_t)(n0 + j) * K + k0 + tx] = l;
    }
}

// segments: x 1024 | w_inp 512 | in_proj 4096 (+bz) | x_proj 192 |
//           xdb-zero 192 | out-bias 1024 | tsplit op 2048 | tsplit wo 512
__global__ void __launch_bounds__(256)
prep_kernel(const float* __restrict__ x, const float* __restrict__ w_inp,
            const float* __restrict__ in_proj, const float* __restrict__ x_proj,
            const float* __restrict__ b_outp, const float* __restrict__ b_inp,
            const float* __restrict__ out_proj, const float* __restrict__ w_outp,
            bf16* xH, bf16* xL, bf16* wiH, bf16* wiL, bf16* ipH, bf16* ipL,
            bf16* w4H, bf16* w4L, bf16* opH, bf16* opL, bf16* woH, bf16* woL,
            float* __restrict__ xdb, float* __restrict__ out, float* __restrict__ bz)
{
    __shared__ float red[256];
    __shared__ float tsm[32][33];
    const int blk = blockIdx.x;
    const int tid = threadIdx.x;
    if (blk < 1024) {
        split4(x, xH, xL, blk * 256 + tid);
    } else if (blk < 1536) {
        split4(w_inp, wiH, wiL, (blk - 1024) * 256 + tid);
    } else if (blk < 5632) {
        const int row = blk - 1536;
        const int i = row * 256 + tid;
        float4 v = reinterpret_cast<const float4*>(in_proj)[i];
        bf16 h0, l0, h1, l1, h2, l2, h3, l3;
        bsplit(v.x, h0, l0); bsplit(v.y, h1, l1);
        bsplit(v.z, h2, l2); bsplit(v.w, h3, l3);
        __nv_bfloat162 hA = {h0, h1}, hB = {h2, h3};
        __nv_bfloat162 lA = {l0, l1}, lB = {l2, l3};
        uint2 hu = {*(uint32_t*)&hA, *(uint32_t*)&hB};
        uint2 lu = {*(uint32_t*)&lA, *(uint32_t*)&lB};
        reinterpret_cast<uint2*>(ipH)[i] = hu;
        reinterpret_cast<uint2*>(ipL)[i] = lu;
        float4 bv = reinterpret_cast<const float4*>(b_inp)[tid];
        red[tid] = v.x * bv.x + v.y * bv.y + v.z * bv.z + v.w * bv.w;
        __syncthreads();
        for (int o = 128; o >= 32; o >>= 1) {
            if (tid < o) red[tid] += red[tid + o];
            __syncthreads();
        }
        if (tid < 32) {
            float r = red[tid];
#pragma unroll
            for (int o = 16; o; o >>= 1) r += __shfl_xor_sync(0xFFFFFFFFu, r, o);
            if (tid == 0) bz[row] = r;
        }
    } else if (blk < 5824) {
        split4(x_proj, w4H, w4L, (blk - 5632) * 256 + tid);
    } else if (blk < 6016) {
        reinterpret_cast<float4*>(xdb)[(blk - 5824) * 256 + tid] =
            make_float4(0.f, 0.f, 0.f, 0.f);
    } else if (blk < 7040) {
        const int i = (blk - 6016) * 256 + tid;
        const int c4 = (i & 127) * 4;
        float4 bv = *reinterpret_cast<const float4*>(&b_outp[c4]);
        reinterpret_cast<float4*>(out)[i] = bv;
    } else if (blk < 9088) {
        const int t = blk - 7040;
        tsplit_seg(out_proj, opH, opL, D_MODEL, D_INNER,
                   (t >> 6) * 32, (t & 63) * 32, tid, tsm);
    } else {
        const int t = blk - 9088;
        tsplit_seg(w_outp, woH, woL, D_MODEL, OUT_SIZE,
                   (t >> 4) * 32, (t & 15) * 32, tid, tsm);
    }
}

// ---------------- conv-shift + silu: bf16 split xc only ----------------
__global__ void __launch_bounds__(256)
conv_kernel(const float* __restrict__ rnn, const float* __restrict__ xz,
            const float* __restrict__ conv_w, const float* __restrict__ conv_b,
            bf16* __restrict__ xch, bf16* __restrict__ xcl)
{
    const size_t idx = (size_t)blockIdx.x * 256 + threadIdx.x;
    const int b = (int)(idx / D_INNER);
    const int d = (int)(idx % D_INNER);
    const size_t srow = (size_t)b * (D_INNER * STATE_W) + (size_t)d * STATE_W;

    float4 cs = *reinterpret_cast<const float4*>(rnn + srow);
    float xi = xz[(size_t)b * (2 * D_INNER) + d];
    float4 w = *reinterpret_cast<const float4*>(conv_w + d * 4);

    float v = cs.y * w.x + cs.z * w.y + cs.w * w.z + xi * w.w + conv_b[d];
    float s = siluf(v);
    bf16 h, l; bsplit(s, h, l);
    xch[idx] = h; xcl[idx] = l;
}

// ======================================================================
// state_kernel: fused dt-dot (fp32) + conv-state shift + SSM + y gating.
// ======================================================================
#define ST_BQ    16
#define ST_SMEM  ((256 * 65 + ST_BQ * 96) * 4)   // 72704 B

__global__ void __launch_bounds__(256, 2)
state_kernel(const float* __restrict__ rnn, const float* __restrict__ xz,
             const float* __restrict__ xdb, const float* __restrict__ w5,
             const float* __restrict__ dtb,
             const bf16* __restrict__ xch, const bf16* __restrict__ xcl,
             const float* __restrict__ A_log, const float* __restrict__ Dp,
             float* __restrict__ ost, bf16* __restrict__ yh, bf16* __restrict__ yl)
{
    extern __shared__ float sm[];
    float* w5s  = sm;
    float* xdbs = sm + 256 * 65;

    const int tid = threadIdx.x;
    const int d0  = blockIdx.x * 256;
    const int b0  = blockIdx.y * ST_BQ;
    const int d   = d0 + tid;

#pragma unroll
    for (int it = 0; it < 16; it++) {
        const int i = it * 256 + tid;
        const int row = i >> 4, c4 = (i & 15) * 4;
        float4 v = *reinterpret_cast<const float4*>(&w5[(size_t)(d0 + row) * DT_RANK + c4]);
        w5s[row * 65 + c4 + 0] = v.x;
        w5s[row * 65 + c4 + 1] = v.y;
        w5s[row * 65 + c4 + 2] = v.z;
        w5s[row * 65 + c4 + 3] = v.w;
    }
#pragma unroll
    for (int it = 0; it < 2; it++) {
        const int i = it * 256 + tid;
        if (i < ST_BQ * 24) {
            const int row = i / 24, c4 = (i % 24) * 4;
            float4 v = *reinterpret_cast<const float4*>(&xdb[(size_t)(b0 + row) * XDB_COLS + c4]);
            *reinterpret_cast<float4*>(&xdbs[row * 96 + c4]) = v;
        }
    }
    __syncthreads();

    const float dtbd = dtb[d];
    const float Dd   = Dp[d];
    float eA[D_STATE];
#pragma unroll
    for (int q = 0; q < 4; q++) {
        float4 a = *reinterpret_cast<const float4*>(&A_log[(size_t)d * D_STATE + q * 4]);
        eA[q * 4 + 0] = __expf(a.x);
        eA[q * 4 + 1] = __expf(a.y);
        eA[q * 4 + 2] = __expf(a.z);
        eA[q * 4 + 3] = __expf(a.w);
    }
    const float* w5r = &w5s[tid * 65];

#pragma unroll 1
    for (int bb = 0; bb < ST_BQ; bb++) {
        const int b = b0 + bb;
        const float* xr = &xdbs[bb * 96];
        float dt = dtbd;
#pragma unroll
        for (int k = 0; k < DT_RANK; k++) dt += xr[k] * w5r[k];
        dt = softplusf(dt);

        const size_t bd = (size_t)b * D_INNER + d;
        const float xc = __bfloat162float(xch[bd]) + __bfloat162float(xcl[bd]);
        const float xi = xz[(size_t)b * (2 * D_INNER) + d];
        const float z  = xz[(size_t)b * (2 * D_INNER) + D_INNER + d];
        const float dtxc = dt * xc;

        const size_t srow = (size_t)b * (D_INNER * STATE_W) + (size_t)d * STATE_W;
        const float4* rr = reinterpret_cast<const float4*>(rnn + srow);
        float4* wr = reinterpret_cast<float4*>(ost + srow);

        float4 cs = rr[0];
        wr[0] = make_float4(cs.y, cs.z, cs.w, xi);

        float y = 0.f;
#pragma unroll
        for (int q = 0; q < 4; q++) {
            float4 s = rr[q + 1];
            float sn[4] = {s.x, s.y, s.z, s.w};
            float on[4];
#pragma unroll
            for (int i = 0; i < 4; i++) {
                const int n = q * 4 + i;
                const float sv = sn[i] * __expf(-dt * eA[n]) + dtxc * xr[DT_RANK + n];
                on[i] = sv;
                y += sv * xr[DT_RANK + D_STATE + n];
            }
            wr[q + 1] = make_float4(on[0], on[1], on[2], on[3]);
        }
        y = (y + Dd * xc) * siluf(z);
        bf16 h, l; bsplit(y, h, l);
        yh[bd] = h; yl[bd] = l;
    }
}

// ---------------- launch ----------------
#define GETP(sym, var) float* var; cudaGetSymbolAddress((void**)&var, sym)
#define GETB(sym, var) bf16* var; cudaGetSymbolAddress((void**)&var, sym)

extern "C" void kernel_launch(void* const* d_in, const int* in_sizes, int n_in,
                              void* d_out, int out_size)
{
    const float* x          = (const float*)d_in[0];
    const float* rnn        = (const float*)d_in[1];
    const float* w_inp      = (const float*)d_in[2];
    const float* b_inp      = (const float*)d_in[3];
    const float* w_outp     = (const float*)d_in[4];
    const float* b_outp     = (const float*)d_in[5];
    const float* in_proj_w  = (const float*)d_in[6];
    const float* conv_w     = (const float*)d_in[7];
    const float* conv_b     = (const float*)d_in[8];
    const float* x_proj_w   = (const float*)d_in[9];
    const float* dt_proj_w  = (const float*)d_in[10];
    const float* dt_proj_b  = (const float*)d_in[11];
    const float* A_log      = (const float*)d_in[12];
    const float* Dp         = (const float*)d_in[13];
    const float* out_proj_w = (const float*)d_in[14];

    float* out = (float*)d_out;
    float* out_states = out + (size_t)BATCH * OUT_SIZE;

    GETP(g_xz, p_xz);   GETP(g_xdb, p_xdb);  GETP(g_bz, p_bz);
    GETB(g_x_hi, xH);   GETB(g_x_lo, xL);
    GETB(g_xc_hi, xcH); GETB(g_xc_lo, xcL);
    GETB(g_y_hi, yH);   GETB(g_y_lo, yL);
    GETB(g_wi_hi, wiH); GETB(g_wi_lo, wiL);
    GETB(g_ip_hi, ipH); GETB(g_ip_lo, ipL);
    GETB(g_wxz_hi, wxH); GETB(g_wxz_lo, wxL);
    GETB(g_w4_hi, w4H); GETB(g_w4_lo, w4L);
    GETB(g_opT_hi, opH); GETB(g_opT_lo, opL);
    GETB(g_woT_hi, woH); GETB(g_woT_lo, woL);
    GETB(g_wf_hi, wfH); GETB(g_wf_lo, wfL);

    cudaFuncSetAttribute(bgemm<1, false, false>, cudaFuncAttributeMaxDynamicSharedMemorySize, TG_SMEM);
    cudaFuncSetAttribute(bgemm<0, true,  false>, cudaFuncAttributeMaxDynamicSharedMemorySize, TG_SMEM);
    cudaFuncSetAttribute(wgemm_dual, cudaFuncAttributeMaxDynamicSharedMemorySize, TG_SMEM);
    cudaFuncSetAttribute(state_kernel, cudaFuncAttributeMaxDynamicSharedMemorySize, ST_SMEM);

    dim3 blk(256);

    // 1) mega prep
    prep_kernel<<<9600, blk>>>(x, w_inp, in_proj_w, x_proj_w, b_outp, b_inp,
                               out_proj_w, w_outp,
                               xH, xL, wiH, wiL, ipH, ipL, w4H, w4L,
                               opH, opL, woH, woL, p_xdb, out, p_bz);
    // 2) W12 + Wf fused weight GEMMs
    wgemm_dual<<<384, blk, TG_SMEM>>>(ipH, ipL, wiH, wiL, wxH, wxL,
                                      woH, woL, opH, opL, wfH, wfL);
    // 3) xz = x @ W12^T + bz
    bgemm<1, false, false><<<dim3(2 * D_INNER / 64, BATCH / 128), blk, TG_SMEM>>>(
        xH, xL, wxH, wxL, p_xz, nullptr, nullptr, p_bz,
        BATCH, 2 * D_INNER, IN_SIZE, IN_SIZE, IN_SIZE, 2 * D_INNER);
    // 4) conv -> xc (bf16 split)
    conv_kernel<<<(BATCH * D_INNER) / 256, blk>>>(rnn, p_xz, conv_w, conv_b, xcH, xcL);
    // 5) xdb = xc @ x_proj^T (2 n-tiles, split-K=8)
    bgemm<0, true, false><<<dim3(2, BATCH / 128, 8), blk, TG_SMEM>>>(
        xcH, xcL, w4H, w4L, p_xdb, nullptr, nullptr, nullptr,
        BATCH, XDB_COLS, D_INNER, D_INNER, D_INNER, XDB_COLS);
    // 6) fused dt + state update + y
    state_kernel<<<dim3(D_INNER / 256, BATCH / ST_BQ), blk, ST_SMEM>>>(
        rnn, p_xz, p_xdb, dt_proj_w, dt_proj_b, xcH, xcL, A_log, Dp,
        out_states, yH, yL);
    // 7) out += y @ Wf^T (split-K=2)
    bgemm<0, true, false><<<dim3(OUT_SIZE / 64, BATCH / 128, 2), blk, TG_SMEM>>>(
        yH, yL, wfH, wfL, out, nullptr, nullptr, nullptr,
        BATCH, OUT_SIZE, D_INNER, D_INNER, D_INNER, OUT_SIZE);
}

// round 16
// speedup vs baseline: 1.0305x; 1.0305x over previous
#include <cuda_runtime.h>
#include <cuda_bf16.h>
#include <math.h>
#include <stdint.h>

#define D_MODEL   1024
#define D_STATE   16
#define D_CONV    4
#define D_INNER   2048
#define DT_RANK   64
#define IN_SIZE   512
#define OUT_SIZE  512
#define BATCH     2048
#define XDB_COLS  96
#define STATE_W   20

typedef __nv_bfloat16 bf16;

// ---------------- fp32 scratch ----------------
__device__ float g_xz[BATCH * 2 * D_INNER];
__device__ float g_xdb[BATCH * XDB_COLS];
__device__ float g_bz[2 * D_INNER];
// ---------------- bf16 split scratch ----------------
__device__ bf16 g_x_hi[BATCH * IN_SIZE],   g_x_lo[BATCH * IN_SIZE];
__device__ bf16 g_xc_hi[BATCH * D_INNER],  g_xc_lo[BATCH * D_INNER];
__device__ bf16 g_y_hi[BATCH * D_INNER],   g_y_lo[BATCH * D_INNER];
__device__ bf16 g_wi_hi[IN_SIZE * D_MODEL],     g_wi_lo[IN_SIZE * D_MODEL];
__device__ bf16 g_ip_hi[2 * D_INNER * D_MODEL], g_ip_lo[2 * D_INNER * D_MODEL];
__device__ bf16 g_wxz_hi[2 * D_INNER * IN_SIZE], g_wxz_lo[2 * D_INNER * IN_SIZE];
__device__ bf16 g_w4_hi[XDB_COLS * D_INNER],    g_w4_lo[XDB_COLS * D_INNER];
__device__ bf16 g_opT_hi[D_INNER * D_MODEL],    g_opT_lo[D_INNER * D_MODEL];
__device__ bf16 g_woT_hi[OUT_SIZE * D_MODEL],   g_woT_lo[OUT_SIZE * D_MODEL];
__device__ bf16 g_wf_hi[OUT_SIZE * D_INNER],    g_wf_lo[OUT_SIZE * D_INNER];

// ---------------- helpers ----------------
__device__ __forceinline__ float softplusf(float x) {
    return (x > 0.f) ? (x + log1pf(__expf(-x))) : log1pf(__expf(x));
}
__device__ __forceinline__ float siluf(float x) {
    return x / (1.f + __expf(-x));
}
__device__ __forceinline__ void bsplit(float v, bf16& h, bf16& l) {
    h = __float2bfloat16_rn(v);
    l = __float2bfloat16_rn(v - __bfloat162float(h));
}
__device__ __forceinline__ void mmabf(float* c, const uint32_t* a, const uint32_t* b) {
    asm volatile(
        "mma.sync.aligned.m16n8k16.row.col.f32.bf16.bf16.f32 "
        "{%0,%1,%2,%3}, {%4,%5,%6,%7}, {%8,%9}, {%0,%1,%2,%3};"
        : "+f"(c[0]), "+f"(c[1]), "+f"(c[2]), "+f"(c[3])
        : "r"(a[0]), "r"(a[1]), "r"(a[2]), "r"(a[3]), "r"(b[0]), "r"(b[1]));
}
__device__ __forceinline__ void cpa16(uint32_t dst, const void* src, bool p) {
    int sz = p ? 16 : 0;
    asm volatile("cp.async.cg.shared.global [%0], [%1], 16, %2;\n"
                 :: "r"(dst), "l"(src), "r"(sz));
}

// ======================================================================
// 2xBF16-split tensor GEMM body (R14-proven). C[M,N] = A[M,K] @ B[N,K]^T.
// BM=128, BN=64, BK=64, 256 thr, warps 4(m)x2(n), warp tile 32x32.
// cp.async 2-stage; smem 108KB/CTA -> 2 CTAs/SM. Scalar LDS frag loads.
// ======================================================================
#define A_TSZ   (128 * 36)
#define B_TSZ   (64 * 36)
#define TG_STAGE (2 * A_TSZ + 2 * B_TSZ)
#define TG_SMEM  (2 * TG_STAGE * 4)      // 110592 B

template<int EPI, bool SPLITK, bool WSPLIT>
__device__ __forceinline__ void
bgemm_body(uint32_t* smbuf, int bx, int by, int bzz, int gz,
           const bf16* __restrict__ Ahi, const bf16* __restrict__ Alo,
           const bf16* __restrict__ Bhi, const bf16* __restrict__ Blo,
           float* __restrict__ C, bf16* __restrict__ Chi, bf16* __restrict__ Clo,
           const float* __restrict__ bias,
           int M, int N, int K, int lda, int ldb, int ldc)
{
    const uint32_t* A32h = reinterpret_cast<const uint32_t*>(Ahi);
    const uint32_t* A32l = reinterpret_cast<const uint32_t*>(Alo);
    const uint32_t* B32h = reinterpret_cast<const uint32_t*>(Bhi);
    const uint32_t* B32l = reinterpret_cast<const uint32_t*>(Blo);
    const int ldap = lda >> 1, ldbp = ldb >> 1;

    const int tid  = threadIdx.x;
    const int lane = tid & 31;
    const int warp = tid >> 5;
    const int wm   = warp & 3;
    const int wn   = warp >> 2;
    const int m0   = by * 128;
    const int n0   = bx * 64;
    const int Kc   = SPLITK ? (K / gz) : K;
    const int k0b  = SPLITK ? (bzz * Kc) : 0;
    const int T    = Kc / 64;

    const int lr = tid >> 3;
    const int lc = (tid & 7) * 4;

    float acc[2][4][4];
#pragma unroll
    for (int i = 0; i < 2; i++)
#pragma unroll
        for (int j = 0; j < 4; j++)
#pragma unroll
            for (int q = 0; q < 4; q++) acc[i][j][q] = 0.f;

    auto fill = [&](int t, int st) {
        uint32_t* Ah = smbuf + st * TG_STAGE;
        uint32_t* Al = Ah + A_TSZ;
        uint32_t* Bh = Al + A_TSZ;
        uint32_t* Bl = Bh + B_TSZ;
        const int kp0 = (k0b + t * 64) >> 1;
#pragma unroll
        for (int it = 0; it < 4; it++) {
            const int row = lr + it * 32;
            const size_t g = (size_t)(m0 + row) * ldap + kp0 + lc;
            cpa16((uint32_t)__cvta_generic_to_shared(&Ah[row * 36 + lc]), A32h + g, true);
            cpa16((uint32_t)__cvta_generic_to_shared(&Al[row * 36 + lc]), A32l + g, true);
        }
#pragma unroll
        for (int it = 0; it < 2; it++) {
            const int row = lr + it * 32;
            const bool p = SPLITK ? ((n0 + row) < N) : true;
            const size_t g = (size_t)(n0 + row) * ldbp + kp0 + lc;
            cpa16((uint32_t)__cvta_generic_to_shared(&Bh[row * 36 + lc]), B32h + g, p);
            cpa16((uint32_t)__cvta_generic_to_shared(&Bl[row * 36 + lc]), B32l + g, p);
        }
    };

    auto compute = [&](int st) {
        uint32_t* Ah = smbuf + st * TG_STAGE;
        uint32_t* Al = Ah + A_TSZ;
        uint32_t* Bh = Al + A_TSZ;
        uint32_t* Bl = Bh + B_TSZ;
#pragma unroll
        for (int ks = 0; ks < 32; ks += 8) {
            uint32_t ah[2][4], al[2][4];
#pragma unroll
            for (int mt = 0; mt < 2; mt++) {
                const int mr = wm * 32 + mt * 16 + (lane >> 2);
                const int kc = ks + (lane & 3);
                ah[mt][0] = Ah[mr * 36 + kc];
                ah[mt][1] = Ah[(mr + 8) * 36 + kc];
                ah[mt][2] = Ah[mr * 36 + kc + 4];
                ah[mt][3] = Ah[(mr + 8) * 36 + kc + 4];
                al[mt][0] = Al[mr * 36 + kc];
                al[mt][1] = Al[(mr + 8) * 36 + kc];
                al[mt][2] = Al[mr * 36 + kc + 4];
                al[mt][3] = Al[(mr + 8) * 36 + kc + 4];
            }
            uint32_t bh[4][2], bl[4][2];
#pragma unroll
            for (int nt = 0; nt < 4; nt++) {
                const int nc = wn * 32 + nt * 8 + (lane >> 2);
                const int kc = ks + (lane & 3);
                bh[nt][0] = Bh[nc * 36 + kc];
                bh[nt][1] = Bh[nc * 36 + kc + 4];
                bl[nt][0] = Bl[nc * 36 + kc];
                bl[nt][1] = Bl[nc * 36 + kc + 4];
            }
#pragma unroll
            for (int mt = 0; mt < 2; mt++)
#pragma unroll
                for (int nt = 0; nt < 4; nt++) {
                    mmabf(acc[mt][nt], ah[mt], bl[nt]);
                    mmabf(acc[mt][nt], al[mt], bh[nt]);
                    mmabf(acc[mt][nt], ah[mt], bh[nt]);
                }
        }
    };

    fill(0, 0);
    asm volatile("cp.async.commit_group;" ::: "memory");
    for (int t = 0; t < T; t++) {
        if (t + 1 < T) {
            fill(t + 1, (t + 1) & 1);
            asm volatile("cp.async.commit_group;" ::: "memory");
            asm volatile("cp.async.wait_group 1;" ::: "memory");
        } else {
            asm volatile("cp.async.wait_group 0;" ::: "memory");
        }
        __syncthreads();
        compute(t & 1);
        __syncthreads();
    }

#pragma unroll
    for (int mt = 0; mt < 2; mt++) {
        const int mr = m0 + wm * 32 + mt * 16 + (lane >> 2);
#pragma unroll
        for (int nt = 0; nt < 4; nt++) {
            const int nc = n0 + wn * 32 + nt * 8 + (lane & 3) * 2;
            float v0 = acc[mt][nt][0], v1 = acc[mt][nt][1];
            float v2 = acc[mt][nt][2], v3 = acc[mt][nt][3];
            if (SPLITK) {
                if (nc < N) {
                    atomicAdd(&C[(size_t)mr * ldc + nc], v0);
                    atomicAdd(&C[(size_t)mr * ldc + nc + 1], v1);
                    atomicAdd(&C[(size_t)(mr + 8) * ldc + nc], v2);
                    atomicAdd(&C[(size_t)(mr + 8) * ldc + nc + 1], v3);
                }
                continue;
            }
            if (EPI >= 1) {
                const float b0 = bias[nc], b1 = bias[nc + 1];
                v0 += b0; v1 += b1; v2 += b0; v3 += b1;
            }
            if (WSPLIT) {
                bf16 h0, l0, h1, l1, h2, l2, h3, l3;
                bsplit(v0, h0, l0); bsplit(v1, h1, l1);
                bsplit(v2, h2, l2); bsplit(v3, h3, l3);
                __nv_bfloat162 ha = {h0, h1}, hb = {h2, h3};
                __nv_bfloat162 la = {l0, l1}, lb = {l2, l3};
                *reinterpret_cast<uint32_t*>(&Chi[(size_t)mr * ldc + nc])       = *(uint32_t*)&ha;
                *reinterpret_cast<uint32_t*>(&Chi[(size_t)(mr + 8) * ldc + nc]) = *(uint32_t*)&hb;
                *reinterpret_cast<uint32_t*>(&Clo[(size_t)mr * ldc + nc])       = *(uint32_t*)&la;
                *reinterpret_cast<uint32_t*>(&Clo[(size_t)(mr + 8) * ldc + nc]) = *(uint32_t*)&lb;
            } else {
                *reinterpret_cast<float2*>(&C[(size_t)mr * ldc + nc])       = make_float2(v0, v1);
                *reinterpret_cast<float2*>(&C[(size_t)(mr + 8) * ldc + nc]) = make_float2(v2, v3);
            }
        }
    }
}

template<int EPI, bool SPLITK, bool WSPLIT>
__global__ void __launch_bounds__(256, 2)
bgemm(const bf16* __restrict__ Ahi, const bf16* __restrict__ Alo,
      const bf16* __restrict__ Bhi, const bf16* __restrict__ Blo,
      float* __restrict__ C, bf16* __restrict__ Chi, bf16* __restrict__ Clo,
      const float* __restrict__ bias,
      int M, int N, int K, int lda, int ldb, int ldc)
{
    extern __shared__ uint32_t smbuf[];
    bgemm_body<EPI, SPLITK, WSPLIT>(smbuf, blockIdx.x, blockIdx.y, blockIdx.z, gridDim.z,
                                    Ahi, Alo, Bhi, Blo, C, Chi, Clo, bias,
                                    M, N, K, lda, ldb, ldc);
}

// ---- dual weight GEMM: W12 (256 CTAs) + Wf (128 CTAs) in one launch ----
__global__ void __launch_bounds__(256, 2)
wgemm_dual(const bf16* ipH, const bf16* ipL, const bf16* wiH, const bf16* wiL,
           bf16* wxH, bf16* wxL,
           const bf16* woH, const bf16* woL, const bf16* opH, const bf16* opL,
           bf16* wfH, bf16* wfL)
{
    extern __shared__ uint32_t smbuf[];
    const int bid = blockIdx.x;
    if (bid < 256) {
        bgemm_body<0, false, true>(smbuf, bid & 7, bid >> 3, 0, 1,
            ipH, ipL, wiH, wiL, nullptr, wxH, wxL, nullptr,
            2 * D_INNER, IN_SIZE, D_MODEL, D_MODEL, D_MODEL, IN_SIZE);
    } else {
        const int t = bid - 256;
        bgemm_body<0, false, true>(smbuf, t & 31, t >> 5, 0, 1,
            woH, woL, opH, opL, nullptr, wfH, wfL, nullptr,
            OUT_SIZE, D_INNER, D_MODEL, D_MODEL, D_MODEL, D_INNER);
    }
}

// ---------------- split helper ----------------
__device__ __forceinline__ void split4(const float* in, bf16* hi, bf16* lo, int i) {
    float4 v = reinterpret_cast<const float4*>(in)[i];
    bf16 h0, l0, h1, l1, h2, l2, h3, l3;
    bsplit(v.x, h0, l0); bsplit(v.y, h1, l1);
    bsplit(v.z, h2, l2); bsplit(v.w, h3, l3);
    __nv_bfloat162 hA = {h0, h1}, hB = {h2, h3};
    __nv_bfloat162 lA = {l0, l1}, lB = {l2, l3};
    uint2 hu = {*(uint32_t*)&hA, *(uint32_t*)&hB};
    uint2 lu = {*(uint32_t*)&lA, *(uint32_t*)&lB};
    reinterpret_cast<uint2*>(hi)[i] = hu;
    reinterpret_cast<uint2*>(lo)[i] = lu;
}

__device__ __forceinline__ void tsplit_seg(const float* in, bf16* hi, bf16* lo,
                                           int K, int N, int k0, int n0,
                                           int tid, float (*tsm)[33])
{
    const int tx = tid & 31, ty = tid >> 5;
#pragma unroll
    for (int j = ty; j < 32; j += 8)
        tsm[j][tx] = in[(size_t)(k0 + j) * N + n0 + tx];
    __syncthreads();
#pragma unroll
    for (int j = ty; j < 32; j += 8) {
        float v = tsm[tx][j];
        bf16 h, l; bsplit(v, h, l);
        hi[(size_t)(n0 + j) * K + k0 + tx] = h;
        lo[(size_t)(n0 + j) * K + k0 + tx] = l;
    }
}

// segments: x 1024 | w_inp 512 | in_proj 4096 (+bz) | x_proj 192 |
//           xdb-zero 192 | out-bias 1024 | tsplit op 2048 | tsplit wo 512
__global__ void __launch_bounds__(256)
prep_kernel(const float* __restrict__ x, const float* __restrict__ w_inp,
            const float* __restrict__ in_proj, const float* __restrict__ x_proj,
            const float* __restrict__ b_outp, const float* __restrict__ b_inp,
            const float* __restrict__ out_proj, const float* __restrict__ w_outp,
            bf16* xH, bf16* xL, bf16* wiH, bf16* wiL, bf16* ipH, bf16* ipL,
            bf16* w4H, bf16* w4L, bf16* opH, bf16* opL, bf16* woH, bf16* woL,
            float* __restrict__ xdb, float* __restrict__ out, float* __restrict__ bz)
{
    __shared__ float red[256];
    __shared__ float tsm[32][33];
    const int blk = blockIdx.x;
    const int tid = threadIdx.x;
    if (blk < 1024) {
        split4(x, xH, xL, blk * 256 + tid);
    } else if (blk < 1536) {
        split4(w_inp, wiH, wiL, (blk - 1024) * 256 + tid);
    } else if (blk < 5632) {
        const int row = blk - 1536;
        const int i = row * 256 + tid;
        float4 v = reinterpret_cast<const float4*>(in_proj)[i];
        bf16 h0, l0, h1, l1, h2, l2, h3, l3;
        bsplit(v.x, h0, l0); bsplit(v.y, h1, l1);
        bsplit(v.z, h2, l2); bsplit(v.w, h3, l3);
        __nv_bfloat162 hA = {h0, h1}, hB = {h2, h3};
        __nv_bfloat162 lA = {l0, l1}, lB = {l2, l3};
        uint2 hu = {*(uint32_t*)&hA, *(uint32_t*)&hB};
        uint2 lu = {*(uint32_t*)&lA, *(uint32_t*)&lB};
        reinterpret_cast<uint2*>(ipH)[i] = hu;
        reinterpret_cast<uint2*>(ipL)[i] = lu;
        float4 bv = reinterpret_cast<const float4*>(b_inp)[tid];
        red[tid] = v.x * bv.x + v.y * bv.y + v.z * bv.z + v.w * bv.w;
        __syncthreads();
        for (int o = 128; o >= 32; o >>= 1) {
            if (tid < o) red[tid] += red[tid + o];
            __syncthreads();
        }
        if (tid < 32) {
            float r = red[tid];
#pragma unroll
            for (int o = 16; o; o >>= 1) r += __shfl_xor_sync(0xFFFFFFFFu, r, o);
            if (tid == 0) bz[row] = r;
        }
    } else if (blk < 5824) {
        split4(x_proj, w4H, w4L, (blk - 5632) * 256 + tid);
    } else if (blk < 6016) {
        reinterpret_cast<float4*>(xdb)[(blk - 5824) * 256 + tid] =
            make_float4(0.f, 0.f, 0.f, 0.f);
    } else if (blk < 7040) {
        const int i = (blk - 6016) * 256 + tid;
        const int c4 = (i & 127) * 4;
        float4 bv = *reinterpret_cast<const float4*>(&b_outp[c4]);
        reinterpret_cast<float4*>(out)[i] = bv;
    } else if (blk < 9088) {
        const int t = blk - 7040;
        tsplit_seg(out_proj, opH, opL, D_MODEL, D_INNER,
                   (t >> 6) * 32, (t & 63) * 32, tid, tsm);
    } else {
        const int t = blk - 9088;
        tsplit_seg(w_outp, woH, woL, D_MODEL, OUT_SIZE,
                   (t >> 4) * 32, (t & 15) * 32, tid, tsm);
    }
}

// ---------------- conv-shift + silu: bf16 split xc only ----------------
__global__ void __launch_bounds__(256)
conv_kernel(const float* __restrict__ rnn, const float* __restrict__ xz,
            const float* __restrict__ conv_w, const float* __restrict__ conv_b,
            bf16* __restrict__ xch, bf16* __restrict__ xcl)
{
    const size_t idx = (size_t)blockIdx.x * 256 + threadIdx.x;
    const int b = (int)(idx / D_INNER);
    const int d = (int)(idx % D_INNER);
    const size_t srow = (size_t)b * (D_INNER * STATE_W) + (size_t)d * STATE_W;

    float4 cs = *reinterpret_cast<const float4*>(rnn + srow);
    float xi = xz[(size_t)b * (2 * D_INNER) + d];
    float4 w = *reinterpret_cast<const float4*>(conv_w + d * 4);

    float v = cs.y * w.x + cs.z * w.y + cs.w * w.z + xi * w.w + conv_b[d];
    float s = siluf(v);
    bf16 h, l; bsplit(s, h, l);
    xch[idx] = h; xcl[idx] = l;
}

// ======================================================================
// state_kernel: fused dt-dot (fp32) + conv-state shift + SSM + y gating.
// ST_BQ=32: w5 staging amortized over 32 batches.
// ======================================================================
#define ST_BQ    32
#define ST_SMEM  ((256 * 65 + ST_BQ * 96) * 4)   // 78848 B

__global__ void __launch_bounds__(256, 2)
state_kernel(const float* __restrict__ rnn, const float* __restrict__ xz,
             const float* __restrict__ xdb, const float* __restrict__ w5,
             const float* __restrict__ dtb,
             const bf16* __restrict__ xch, const bf16* __restrict__ xcl,
             const float* __restrict__ A_log, const float* __restrict__ Dp,
             float* __restrict__ ost, bf16* __restrict__ yh, bf16* __restrict__ yl)
{
    extern __shared__ float sm[];
    float* w5s  = sm;
    float* xdbs = sm + 256 * 65;

    const int tid = threadIdx.x;
    const int d0  = blockIdx.x * 256;
    const int b0  = blockIdx.y * ST_BQ;
    const int d   = d0 + tid;

#pragma unroll
    for (int it = 0; it < 16; it++) {
        const int i = it * 256 + tid;
        const int row = i >> 4, c4 = (i & 15) * 4;
        float4 v = *reinterpret_cast<const float4*>(&w5[(size_t)(d0 + row) * DT_RANK + c4]);
        w5s[row * 65 + c4 + 0] = v.x;
        w5s[row * 65 + c4 + 1] = v.y;
        w5s[row * 65 + c4 + 2] = v.z;
        w5s[row * 65 + c4 + 3] = v.w;
    }
#pragma unroll
    for (int it = 0; it < 3; it++) {
        const int i = it * 256 + tid;
        if (i < ST_BQ * 24) {
            const int row = i / 24, c4 = (i % 24) * 4;
            float4 v = *reinterpret_cast<const float4*>(&xdb[(size_t)(b0 + row) * XDB_COLS + c4]);
            *reinterpret_cast<float4*>(&xdbs[row * 96 + c4]) = v;
        }
    }
    __syncthreads();

    const float dtbd = dtb[d];
    const float Dd   = Dp[d];
    float eA[D_STATE];
#pragma unroll
    for (int q = 0; q < 4; q++) {
        float4 a = *reinterpret_cast<const float4*>(&A_log[(size_t)d * D_STATE + q * 4]);
        eA[q * 4 + 0] = __expf(a.x);
        eA[q * 4 + 1] = __expf(a.y);
        eA[q * 4 + 2] = __expf(a.z);
        eA[q * 4 + 3] = __expf(a.w);
    }
    const float* w5r = &w5s[tid * 65];

#pragma unroll 1
    for (int bb = 0; bb < ST_BQ; bb++) {
        const int b = b0 + bb;
        const float* xr = &xdbs[bb * 96];
        float dt = dtbd;
#pragma unroll
        for (int k = 0; k < DT_RANK; k++) dt += xr[k] * w5r[k];
        dt = softplusf(dt);

        const size_t bd = (size_t)b * D_INNER + d;
        const float xc = __bfloat162float(xch[bd]) + __bfloat162float(xcl[bd]);
        const float xi = xz[(size_t)b * (2 * D_INNER) + d];
        const float z  = xz[(size_t)b * (2 * D_INNER) + D_INNER + d];
        const float dtxc = dt * xc;

        const size_t srow = (size_t)b * (D_INNER * STATE_W) + (size_t)d * STATE_W;
        const float4* rr = reinterpret_cast<const float4*>(rnn + srow);
        float4* wr = reinterpret_cast<float4*>(ost + srow);

        float4 cs = rr[0];
        wr[0] = make_float4(cs.y, cs.z, cs.w, xi);

        float y = 0.f;
#pragma unroll
        for (int q = 0; q < 4; q++) {
            float4 s = rr[q + 1];
            float sn[4] = {s.x, s.y, s.z, s.w};
            float on[4];
#pragma unroll
            for (int i = 0; i < 4; i++) {
                const int n = q * 4 + i;
                const float sv = sn[i] * __expf(-dt * eA[n]) + dtxc * xr[DT_RANK + n];
                on[i] = sv;
                y += sv * xr[DT_RANK + D_STATE + n];
            }
            wr[q + 1] = make_float4(on[0], on[1], on[2], on[3]);
        }
        y = (y + Dd * xc) * siluf(z);
        bf16 h, l; bsplit(y, h, l);
        yh[bd] = h; yl[bd] = l;
    }
}

// ---------------- launch ----------------
#define GETP(sym, var) float* var; cudaGetSymbolAddress((void**)&var, sym)
#define GETB(sym, var) bf16* var; cudaGetSymbolAddress((void**)&var, sym)

extern "C" void kernel_launch(void* const* d_in, const int* in_sizes, int n_in,
                              void* d_out, int out_size)
{
    const float* x          = (const float*)d_in[0];
    const float* rnn        = (const float*)d_in[1];
    const float* w_inp      = (const float*)d_in[2];
    const float* b_inp      = (const float*)d_in[3];
    const float* w_outp     = (const float*)d_in[4];
    const float* b_outp     = (const float*)d_in[5];
    const float* in_proj_w  = (const float*)d_in[6];
    const float* conv_w     = (const float*)d_in[7];
    const float* conv_b     = (const float*)d_in[8];
    const float* x_proj_w   = (const float*)d_in[9];
    const float* dt_proj_w  = (const float*)d_in[10];
    const float* dt_proj_b  = (const float*)d_in[11];
    const float* A_log      = (const float*)d_in[12];
    const float* Dp         = (const float*)d_in[13];
    const float* out_proj_w = (const float*)d_in[14];

    float* out = (float*)d_out;
    float* out_states = out + (size_t)BATCH * OUT_SIZE;

    GETP(g_xz, p_xz);   GETP(g_xdb, p_xdb);  GETP(g_bz, p_bz);
    GETB(g_x_hi, xH);   GETB(g_x_lo, xL);
    GETB(g_xc_hi, xcH); GETB(g_xc_lo, xcL);
    GETB(g_y_hi, yH);   GETB(g_y_lo, yL);
    GETB(g_wi_hi, wiH); GETB(g_wi_lo, wiL);
    GETB(g_ip_hi, ipH); GETB(g_ip_lo, ipL);
    GETB(g_wxz_hi, wxH); GETB(g_wxz_lo, wxL);
    GETB(g_w4_hi, w4H); GETB(g_w4_lo, w4L);
    GETB(g_opT_hi, opH); GETB(g_opT_lo, opL);
    GETB(g_woT_hi, woH); GETB(g_woT_lo, woL);
    GETB(g_wf_hi, wfH); GETB(g_wf_lo, wfL);

    cudaFuncSetAttribute(bgemm<1, false, false>, cudaFuncAttributeMaxDynamicSharedMemorySize, TG_SMEM);
    cudaFuncSetAttribute(bgemm<0, true,  false>, cudaFuncAttributeMaxDynamicSharedMemorySize, TG_SMEM);
    cudaFuncSetAttribute(wgemm_dual, cudaFuncAttributeMaxDynamicSharedMemorySize, TG_SMEM);
    cudaFuncSetAttribute(state_kernel, cudaFuncAttributeMaxDynamicSharedMemorySize, ST_SMEM);

    dim3 blk(256);

    // 1) mega prep
    prep_kernel<<<9600, blk>>>(x, w_inp, in_proj_w, x_proj_w, b_outp, b_inp,
                               out_proj_w, w_outp,
                               xH, xL, wiH, wiL, ipH, ipL, w4H, w4L,
                               opH, opL, woH, woL, p_xdb, out, p_bz);
    // 2) W12 + Wf fused weight GEMMs
    wgemm_dual<<<384, blk, TG_SMEM>>>(ipH, ipL, wiH, wiL, wxH, wxL,
                                      woH, woL, opH, opL, wfH, wfL);
    // 3) xz = x @ W12^T + bz
    bgemm<1, false, false><<<dim3(2 * D_INNER / 64, BATCH / 128), blk, TG_SMEM>>>(
        xH, xL, wxH, wxL, p_xz, nullptr, nullptr, p_bz,
        BATCH, 2 * D_INNER, IN_SIZE, IN_SIZE, IN_SIZE, 2 * D_INNER);
    // 4) conv -> xc (bf16 split)
    conv_kernel<<<(BATCH * D_INNER) / 256, blk>>>(rnn, p_xz, conv_w, conv_b, xcH, xcL);
    // 5) xdb = xc @ x_proj^T (2 n-tiles, split-K=8)
    bgemm<0, true, false><<<dim3(2, BATCH / 128, 8), blk, TG_SMEM>>>(
        xcH, xcL, w4H, w4L, p_xdb, nullptr, nullptr, nullptr,
        BATCH, XDB_COLS, D_INNER, D_INNER, D_INNER, XDB_COLS);
    // 6) fused dt + state update + y
    state_kernel<<<dim3(D_INNER / 256, BATCH / ST_BQ), blk, ST_SMEM>>>(
        rnn, p_xz, p_xdb, dt_proj_w, dt_proj_b, xcH, xcL, A_log, Dp,
        out_states, yH, yL);
    // 7) out += y @ Wf^T (split-K=4; 512 CTAs)
    bgemm<0, true, false><<<dim3(OUT_SIZE / 64, BATCH / 128, 4), blk, TG_SMEM>>>(
        yH, yL, wfH, wfL, out, nullptr, nullptr, nullptr,
        BATCH, OUT_SIZE, D_INNER, D_INNER, D_INNER, OUT_SIZE);
}